// round 1
// baseline (speedup 1.0000x reference)
#include <cuda_runtime.h>
#include <math.h>
#include <float.h>

#define BATCH 8
#define NPT   1024
#define BN    8192            // BATCH * NPT
#define TOT   8388608         // BATCH * NPT * NPT
#define T4    2097152         // TOT / 4
#define GRID  148
#define BLOCK 256

// -------- persistent device state (re-initialized every launch) ----------
__device__ __align__(16) float g_K [TOT];   // K  row-major  [b][i][j]
__device__ __align__(16) float g_Kt[TOT];   // K^T row-major [b][j][i]
__device__ __align__(16) float g_u [2 * BN];
__device__ __align__(16) float g_v [2 * BN];
__device__ __align__(16) float g_a [BN];
__device__ __align__(16) float g_b [BN];
__device__ float g_sum[16];                 // [0..7]=sum(a)  [8..15]=sum(b)
__device__ int   g_maxM[BATCH];             // float bits, values >= 0
__device__ int   g_bad;
__device__ int   g_maxdiff[10];             // float bits, values >= 0
__device__ unsigned g_barCount;             // monotonic across launches
__device__ volatile unsigned g_barGen;      // monotonic across launches

// -------- grid-wide barrier (all blocks resident: grid <= SM count) ------
__device__ __forceinline__ void grid_barrier(int nb) {
    __threadfence();              // flush my stores to L2 + invalidate L1
    __syncthreads();
    if (threadIdx.x == 0) {
        unsigned g = g_barGen;
        unsigned t = atomicAdd(&g_barCount, 1u);
        if (t % (unsigned)nb == (unsigned)(nb - 1)) {
            __threadfence();
            g_barGen = g + 1u;
        } else {
            while (g_barGen == g) { __nanosleep(64); }
        }
    }
    __syncthreads();
}

// -------- one warp computes dot(mat_row[0..1023], vec[0..1023]) ----------
__device__ __forceinline__ float warp_row_dot(const float* __restrict__ row,
                                              const float* __restrict__ vec,
                                              int lane) {
    const float4* m4 = (const float4*)row;
    const float4* v4 = (const float4*)vec;
    float acc0 = 0.f, acc1 = 0.f;
#pragma unroll
    for (int s = 0; s < 8; s += 2) {
        float4 a = m4[lane + 32 * s];
        float4 b = v4[lane + 32 * s];
        float4 c = m4[lane + 32 * (s + 1)];
        float4 d = v4[lane + 32 * (s + 1)];
        acc0 = fmaf(a.x, b.x, fmaf(a.y, b.y, fmaf(a.z, b.z, fmaf(a.w, b.w, acc0))));
        acc1 = fmaf(c.x, d.x, fmaf(c.y, d.y, fmaf(c.z, d.z, fmaf(c.w, d.w, acc1))));
    }
    float acc = acc0 + acc1;
#pragma unroll
    for (int o = 16; o; o >>= 1) acc += __shfl_xor_sync(0xffffffffu, acc, o);
    return acc;
}

// half Sinkhorn iteration: out[r] = marg[r] / dot(mat_row_r, invec_batch)
__device__ __forceinline__ void half_iter(const float* __restrict__ mat,
                                          const float* __restrict__ invec,
                                          const float* __restrict__ marg,
                                          float* __restrict__ outvec,
                                          int gw, int lane, int nw) {
    for (int r = gw; r < BN; r += nw) {
        int b = r >> 10;
        float dot = warp_row_dot(mat + ((size_t)r << 10), invec + (b << 10), lane);
        if (lane == 0) {
            float o = marg[r] / dot;
            if (dot == 0.0f || !(fabsf(o) <= FLT_MAX)) atomicOr(&g_bad, 1);
            outvec[r] = o;
        }
    }
}

__global__ void __launch_bounds__(BLOCK, 1)
sot_kernel(const float* __restrict__ coord1, const float* __restrict__ prob1,
           const float* __restrict__ coord2, const float* __restrict__ prob2,
           float* __restrict__ Pout) {
    const int tid  = threadIdx.x;
    const int bid  = blockIdx.x;
    const int nb   = gridDim.x;
    const int nthr = nb * BLOCK;
    const int gtid = bid * BLOCK + tid;
    const int lane = tid & 31;
    const int wid  = tid >> 5;
    const int gw   = gtid >> 5;
    const int nw   = nthr >> 5;

    __shared__ float s_tile[32][33];
    __shared__ float s_red[32];

    // ---------------- Phase 0a: init state + prob sums --------------------
    for (int r = gtid; r < BN; r += nthr) {
        g_u[r] = 1.0f / 1024.0f;
        g_v[r] = 1.0f / 1024.0f;
    }
    if (gtid < BATCH)                g_maxM[gtid] = 0;
    if (gtid == BATCH)               g_bad = 0;
    if (gtid >= 16 && gtid < 26)     g_maxdiff[gtid - 16] = 0;

    if (bid < 16) {
        int b = bid & 7;
        const float* src = (bid < 8 ? prob1 : prob2) + (b << 10);
        float s = 0.f;
        for (int j = tid; j < NPT; j += BLOCK) s += src[j] + 1e-8f;
#pragma unroll
        for (int o = 16; o; o >>= 1) s += __shfl_xor_sync(0xffffffffu, s, o);
        if (lane == 0) s_red[wid] = s;
        __syncthreads();
        if (wid == 0) {
            float t = (lane < (BLOCK >> 5)) ? s_red[lane] : 0.f;
#pragma unroll
            for (int o = 16; o; o >>= 1) t += __shfl_xor_sync(0xffffffffu, t, o);
            if (lane == 0) g_sum[bid] = t;
        }
    }
    grid_barrier(nb);

    // ---------------- Phase 0b: a,b vectors + per-batch max(M) ------------
    for (int r = gtid; r < BN; r += nthr) {
        int b = r >> 10;
        g_a[r] = (prob1[r] + 1e-8f) / g_sum[b];
        g_b[r] = (prob2[r] + 1e-8f) / g_sum[8 + b];
    }
    for (int r = gw; r < BN; r += nw) {
        int b = r >> 10;
        float x0 = coord1[2 * r], x1 = coord1[2 * r + 1];
        const float2* y = (const float2*)(coord2 + (b << 11));
        float m = 0.f;
        for (int j = lane; j < NPT; j += 32) {
            float2 yy = y[j];
            float d0 = x0 - yy.x, d1 = x1 - yy.y;
            m = fmaxf(m, d0 * d0 + d1 * d1);
        }
#pragma unroll
        for (int o = 16; o; o >>= 1) m = fmaxf(m, __shfl_xor_sync(0xffffffffu, m, o));
        if (lane == 0) atomicMax(&g_maxM[b], __float_as_int(m));
    }
    grid_barrier(nb);

    // ---------------- Phase 1: materialize K and K^T (32x32 tiles) --------
    for (int t = bid; t < 8192; t += nb) {
        int b  = t >> 10;
        int ti = (t >> 5) & 31;
        int tj = t & 31;
        float invmax = 1.0f / __int_as_float(g_maxM[b]);
        int i0 = ti << 5, j0 = tj << 5;
        const float2* cx = (const float2*)(coord1 + (b << 11));
        const float2* cy = (const float2*)(coord2 + (b << 11));
#pragma unroll
        for (int s = 0; s < 4; ++s) {
            int e  = tid + (s << 8);
            int li = e >> 5, lj = e & 31;
            int i = i0 + li, j = j0 + lj;
            float2 xi = cx[i];
            float2 yj = cy[j];
            float d0 = xi.x - yj.x, d1 = xi.y - yj.y;
            float Mn = (d0 * d0 + d1 * d1) * invmax;     // M / max(M)
            float k  = expf(Mn * -10.0f);                // exp(-Mn/0.1)
            g_K[((size_t)b << 20) + ((size_t)i << 10) + j] = k;
            s_tile[li][lj] = k;
        }
        __syncthreads();
#pragma unroll
        for (int s = 0; s < 4; ++s) {
            int e  = tid + (s << 8);
            int lj = e >> 5, li = e & 31;                // transpose roles
            g_Kt[((size_t)b << 20) + ((size_t)(j0 + lj) << 10) + (i0 + li)] =
                s_tile[li][lj];
        }
        __syncthreads();
    }
    grid_barrier(nb);

    // ---------------- Phase 2: Sinkhorn iterations ------------------------
    int par = 0;
    for (int c = 0; c < 10; ++c) {
        bool bad = false;
        for (int it = 0; it < 10; ++it) {
            const float* ucur  = g_u + par * BN;
            float*       vnext = g_v + (par ^ 1) * BN;
            float*       unext = g_u + (par ^ 1) * BN;
            // v1 = b / (K^T u)
            half_iter(g_Kt, ucur, g_b, vnext, gw, lane, nw);
            grid_barrier(nb);
            // u1 = a / (K v1)
            half_iter(g_K, vnext, g_a, unext, gw, lane, nw);
            grid_barrier(nb);
            if (*(volatile int*)&g_bad) { bad = true; break; }
            par ^= 1;   // commit
        }
        if (bad) {
            if (c == 0) {   // P never updated: output P0 = K / n^2
                const float4* K4 = (const float4*)g_K;
                float4* O4 = (float4*)Pout;
                const float sc = 1.0f / 1048576.0f;      // 2^-20 exact
                for (int e = gtid; e < T4; e += nthr) {
                    float4 k = K4[e];
                    O4[e] = make_float4(k.x * sc, k.y * sc, k.z * sc, k.w * sc);
                }
            }
            return;   // previous chunk's P already lives in Pout
        }
        // -------- P phase: Pn = u * K * v^T, maxdiff vs previous P --------
        {
            const float* uc = g_u + par * BN;
            const float* vc = g_v + par * BN;
            const float4* K4 = (const float4*)g_K;
            float4* O4 = (float4*)Pout;
            const float sc = 1.0f / 1048576.0f;
            float lm = 0.f;
            for (int e = gtid; e < T4; e += nthr) {
                int row = e >> 8;                 // b*1024 + i
                int b   = e >> 18;
                float u = uc[row];
                float4 k  = K4[e];
                float4 vv = ((const float4*)(vc + (b << 10)))[e & 255];
                float4 pn;
                pn.x = u * k.x * vv.x;
                pn.y = u * k.y * vv.y;
                pn.z = u * k.z * vv.z;
                pn.w = u * k.w * vv.w;
                float4 po;
                if (c == 0) {
                    po.x = k.x * sc; po.y = k.y * sc;
                    po.z = k.z * sc; po.w = k.w * sc;
                } else {
                    po = O4[e];
                }
                float d = fmaxf(fmaxf(fabsf(pn.x - po.x), fabsf(pn.y - po.y)),
                                fmaxf(fabsf(pn.z - po.z), fabsf(pn.w - po.w)));
                lm = fmaxf(lm, d);
                O4[e] = pn;
            }
#pragma unroll
            for (int o = 16; o; o >>= 1) lm = fmaxf(lm, __shfl_xor_sync(0xffffffffu, lm, o));
            if (lane == 0) s_red[wid] = lm;
            __syncthreads();
            if (wid == 0) {
                float t = (lane < (BLOCK >> 5)) ? s_red[lane] : 0.f;
#pragma unroll
                for (int o = 16; o; o >>= 1) t = fmaxf(t, __shfl_xor_sync(0xffffffffu, t, o));
                if (lane == 0) atomicMax(&g_maxdiff[c], __float_as_int(t));
            }
            __syncthreads();
        }
        grid_barrier(nb);
        float md = __int_as_float(*(volatile int*)&g_maxdiff[c]);
        if (md < 1e-3f) return;     // converged: done for all future chunks
    }
}

extern "C" void kernel_launch(void* const* d_in, const int* in_sizes, int n_in,
                              void* d_out, int out_size) {
    // robust input mapping: coords have 16384 elements, probs have 8192
    const float* c1 = nullptr; const float* p1 = nullptr;
    const float* c2 = nullptr; const float* p2 = nullptr;
    for (int i = 0; i < n_in; ++i) {
        if (in_sizes[i] == BATCH * NPT * 2) {
            if (!c1) c1 = (const float*)d_in[i]; else c2 = (const float*)d_in[i];
        } else if (in_sizes[i] == BATCH * NPT) {
            if (!p1) p1 = (const float*)d_in[i]; else p2 = (const float*)d_in[i];
        }
    }
    sot_kernel<<<GRID, BLOCK>>>(c1, p1, c2, p2, (float*)d_out);
}

// round 2
// speedup vs baseline: 1.1520x; 1.1520x over previous
#include <cuda_runtime.h>
#include <math.h>
#include <float.h>

#define BATCH 8
#define NPT   1024
#define BN    8192            // BATCH * NPT
#define TOT   8388608         // BATCH * NPT * NPT
#define T4    2097152         // TOT / 4
#define GRID  148
#define BLOCK 512
#define NWB   (BLOCK/32)      // 16 warps per block
#define NTHR  (GRID*BLOCK)

// -------- persistent device state (re-initialized every launch) ----------
__device__ __align__(16) float g_K [TOT];   // K  row-major  [b][i][j]
__device__ __align__(16) float g_Kt[TOT];   // K^T row-major [b][j][i]
__device__ __align__(16) float g_u [2 * BN];
__device__ __align__(16) float g_v [2 * BN];
__device__ __align__(16) float g_a [BN];
__device__ __align__(16) float g_b [BN];
__device__ float g_sum[16];                 // [0..7]=sum(a)  [8..15]=sum(b)
__device__ int   g_maxM[BATCH];             // float bits, values >= 0
__device__ int   g_bad;
__device__ int   g_maxdiff[10];             // float bits, values >= 0
__device__ unsigned g_warpCnt[GRID];        // light barrier: per-block arrivals
__device__ unsigned g_blkCnt;               // light barrier: global arrivals
__device__ unsigned g_hvyCount;             // heavy barrier (monotonic)
__device__ volatile unsigned g_hvyGen;      // heavy barrier (monotonic)

// -------- heavy barrier (threadfence; used only in setup phases) ---------
__device__ __forceinline__ void heavy_barrier() {
    __threadfence();
    __syncthreads();
    if (threadIdx.x == 0) {
        unsigned g = g_hvyGen;
        unsigned t = atomicAdd(&g_hvyCount, 1u);
        if (t % (unsigned)GRID == (unsigned)(GRID - 1)) {
            __threadfence();
            g_hvyGen = g + 1u;
        } else {
            while (g_hvyGen == g) {}
        }
    }
    __syncthreads();
}

// -------- release/acquire primitives for the light barrier ---------------
__device__ __forceinline__ void rel_inc(unsigned* p) {
    asm volatile("red.release.gpu.global.add.u32 [%0], %1;"
                 :: "l"(p), "r"(1u) : "memory");
}
__device__ __forceinline__ unsigned acq_ld(const unsigned* p) {
    unsigned v;
    asm volatile("ld.acquire.gpu.global.u32 %0, [%1];"
                 : "=r"(v) : "l"(p) : "memory");
    return v;
}

// -------- half Sinkhorn pass: rows [r_lo,r_hi) of one batch --------------
// invec preloaded into 32 regs/lane via .cv (cross-SM fresh). STREAM picks
// evict-first loads (Kt pass) vs cached loads (K pass, L1-resident rows).
template<bool STREAM>
__device__ __forceinline__ void half_pass(const float* __restrict__ mat,
                                          const float* __restrict__ invec,
                                          const float* __restrict__ marg,
                                          float* __restrict__ outv,
                                          int r_lo, int r_hi, int lane, int wid)
{
    float4 vr[8];
    const float4* v4 = (const float4*)invec;
#pragma unroll
    for (int s = 0; s < 8; ++s) vr[s] = __ldcv(v4 + lane + 32 * s);
    for (int r = r_lo + wid; r < r_hi; r += NWB) {
        const float4* m4 = (const float4*)(mat + ((size_t)r << 10));
        float a0 = 0.f, a1 = 0.f;
#pragma unroll
        for (int s = 0; s < 8; s += 2) {
            float4 k0 = STREAM ? __ldcs(m4 + lane + 32 * s)
                               : __ldg (m4 + lane + 32 * s);
            float4 k1 = STREAM ? __ldcs(m4 + lane + 32 * (s + 1))
                               : __ldg (m4 + lane + 32 * (s + 1));
            a0 = fmaf(k0.x, vr[s].x, fmaf(k0.y, vr[s].y,
                 fmaf(k0.z, vr[s].z, fmaf(k0.w, vr[s].w, a0))));
            a1 = fmaf(k1.x, vr[s+1].x, fmaf(k1.y, vr[s+1].y,
                 fmaf(k1.z, vr[s+1].z, fmaf(k1.w, vr[s+1].w, a1))));
        }
        float acc = a0 + a1;
#pragma unroll
        for (int o = 16; o; o >>= 1) acc += __shfl_xor_sync(0xffffffffu, acc, o);
        if (lane == 0) {
            float o = marg[r] / acc;
            if (acc == 0.0f || !(fabsf(o) <= FLT_MAX)) atomicOr(&g_bad, 1);
            outv[r] = o;
        }
    }
}

__global__ void __launch_bounds__(BLOCK, 1)
sot_kernel(const float* __restrict__ coord1, const float* __restrict__ prob1,
           const float* __restrict__ coord2, const float* __restrict__ prob2,
           float* __restrict__ Pout)
{
    const int tid  = threadIdx.x;
    const int bid  = blockIdx.x;
    const int gtid = bid * BLOCK + tid;
    const int lane = tid & 31;
    const int wid  = tid >> 5;

    __shared__ __align__(16) float s_stage[BN];   // 32KB: v-stage / tile buf
    __shared__ float s_red[NWB];
    __shared__ int   s_flag;

    // ---------------- Phase 0a: init state + prob sums --------------------
    for (int r = gtid; r < BN; r += NTHR) {
        g_u[r] = 1.0f / 1024.0f;
        g_v[r] = 1.0f / 1024.0f;
    }
    if (gtid < GRID)                 g_warpCnt[gtid] = 0;
    if (gtid == GRID)                g_blkCnt = 0;
    if (gtid >= 256 && gtid < 264)   g_maxM[gtid - 256] = 0;
    if (gtid == 264)                 g_bad = 0;
    if (gtid >= 272 && gtid < 282)   g_maxdiff[gtid - 272] = 0;

    if (bid < 16) {
        int b = bid & 7;
        const float* src = (bid < 8 ? prob1 : prob2) + (b << 10);
        float s = 0.f;
        for (int j = tid; j < NPT; j += BLOCK) s += src[j] + 1e-8f;
#pragma unroll
        for (int o = 16; o; o >>= 1) s += __shfl_xor_sync(0xffffffffu, s, o);
        if (lane == 0) s_red[wid] = s;
        __syncthreads();
        if (wid == 0) {
            float t = (lane < NWB) ? s_red[lane] : 0.f;
#pragma unroll
            for (int o = 16; o; o >>= 1) t += __shfl_xor_sync(0xffffffffu, t, o);
            if (lane == 0) g_sum[bid] = t;
        }
    }
    heavy_barrier();

    // ---------------- Phase 0b: a,b vectors + per-batch max(M) ------------
    for (int r = gtid; r < BN; r += NTHR) {
        int b = r >> 10;
        g_a[r] = (prob1[r] + 1e-8f) / g_sum[b];
        g_b[r] = (prob2[r] + 1e-8f) / g_sum[8 + b];
    }
    {
        int gw = gtid >> 5, nw = NTHR >> 5;
        for (int r = gw; r < BN; r += nw) {
            int b = r >> 10;
            float x0 = coord1[2 * r], x1 = coord1[2 * r + 1];
            const float2* y = (const float2*)(coord2 + (b << 11));
            float m = 0.f;
            for (int j = lane; j < NPT; j += 32) {
                float2 yy = y[j];
                float d0 = x0 - yy.x, d1 = x1 - yy.y;
                m = fmaxf(m, d0 * d0 + d1 * d1);
            }
#pragma unroll
            for (int o = 16; o; o >>= 1) m = fmaxf(m, __shfl_xor_sync(0xffffffffu, m, o));
            if (lane == 0) atomicMax(&g_maxM[b], __float_as_int(m));
        }
    }
    heavy_barrier();

    // ---------------- Phase 1: materialize K and K^T (32x32 tiles) --------
    for (int t = bid; t < 8192; t += GRID) {
        int b  = t >> 10;
        int ti = (t >> 5) & 31;
        int tj = t & 31;
        float invmax = 1.0f / __int_as_float(g_maxM[b]);
        int i0 = ti << 5, j0 = tj << 5;
        const float2* cx = (const float2*)(coord1 + (b << 11));
        const float2* cy = (const float2*)(coord2 + (b << 11));
#pragma unroll
        for (int s = 0; s < 2; ++s) {
            int e  = tid + (s << 9);
            int li = e >> 5, lj = e & 31;
            float2 xi = cx[i0 + li];
            float2 yj = cy[j0 + lj];
            float d0 = xi.x - yj.x, d1 = xi.y - yj.y;
            float Mn = (d0 * d0 + d1 * d1) * invmax;
            float k  = expf(Mn * -10.0f);
            g_K[((size_t)b << 20) + ((size_t)(i0 + li) << 10) + (j0 + lj)] = k;
            s_stage[li * 33 + lj] = k;
        }
        __syncthreads();
#pragma unroll
        for (int s = 0; s < 2; ++s) {
            int e  = tid + (s << 9);
            int lj = e >> 5, li = e & 31;
            g_Kt[((size_t)b << 20) + ((size_t)(j0 + lj) << 10) + (i0 + li)] =
                s_stage[li * 33 + lj];
        }
        __syncthreads();
    }
    heavy_barrier();

    // ---------------- Phase 2: Sinkhorn iterations ------------------------
    // block -> batch mapping (contiguous rows, static across iterations for
    // L1 residency of this block's K rows)
    int myb  = (bid * BATCH) / GRID;
    int blk0 = (myb * GRID + BATCH - 1) / BATCH;
    int blk1 = ((myb + 1) * GRID + BATCH - 1) / BATCH;
    int nbb  = blk1 - blk0;
    int lidx = bid - blk0;
    int r_lo = (lidx * NPT) / nbb;
    int r_hi = ((lidx + 1) * NPT) / nbb;

    const float* matK  = g_K  + ((size_t)myb << 20);
    const float* matKt = g_Kt + ((size_t)myb << 20);
    const float* aB = g_a + (myb << 10);
    const float* bB = g_b + (myb << 10);

    unsigned ph = 0;
    int par = 0;

    auto lbar = [&](const int* sample) -> int {
        ph++;
        if (lane == 0) rel_inc(&g_warpCnt[bid]);
        if (tid == 0) {
            while (acq_ld(&g_warpCnt[bid]) < ph * NWB) {}
            rel_inc(&g_blkCnt);
            while (acq_ld(&g_blkCnt) < ph * (unsigned)GRID) {}
            s_flag = sample ? __ldcv(sample) : 0;
        }
        __syncthreads();
        return s_flag;
    };

    for (int c = 0; c < 10; ++c) {
        bool bad = false;
        for (int it = 0; it < 10; ++it) {
            const float* uc = g_u + par * BN + (myb << 10);
            float*       vn = g_v + (par ^ 1) * BN + (myb << 10);
            float*       un = g_u + (par ^ 1) * BN + (myb << 10);
            // v1 = b / (K^T u)   (streaming: don't evict resident K rows)
            half_pass<true >(matKt, uc, bB, vn, r_lo, r_hi, lane, wid);
            lbar(nullptr);
            // u1 = a / (K v1)    (cached: rows L1-resident across iters)
            half_pass<false>(matK , vn, aB, un, r_lo, r_hi, lane, wid);
            if (lbar(&g_bad)) { bad = true; break; }
            par ^= 1;   // commit
        }
        if (bad) {
            if (c == 0) {   // P never updated: output P0 = K / n^2
                const float4* K4 = (const float4*)g_K;
                float4* O4 = (float4*)Pout;
                const float sc = 1.0f / 1048576.0f;
                for (int e = gtid; e < T4; e += NTHR) {
                    float4 k = __ldcs(K4 + e);
                    O4[e] = make_float4(k.x * sc, k.y * sc, k.z * sc, k.w * sc);
                }
            }
            return;   // previous chunk's P already lives in Pout
        }
        // -------- P phase: Pn = u * K * v^T, maxdiff vs previous P --------
        {
            const float* ucg = g_u + par * BN;
            const float4* vs4g = (const float4*)(g_v + par * BN);
            float4* st4 = (float4*)s_stage;
            for (int e2 = tid; e2 < BN / 4; e2 += BLOCK)
                st4[e2] = __ldcv(vs4g + e2);
            __syncthreads();

            const float4* K4 = (const float4*)g_K;
            float4* O4 = (float4*)Pout;
            const float sc = 1.0f / 1048576.0f;
            float lm = 0.f;
            for (int e = gtid; e < T4; e += NTHR) {
                int row = e >> 8;                 // b*1024 + i
                int b   = e >> 18;
                float u = __ldcv(ucg + row);
                float4 k  = __ldcs(K4 + e);
                float4 vv = st4[(b << 8) + (e & 255)];
                float4 pn;
                pn.x = u * k.x * vv.x;
                pn.y = u * k.y * vv.y;
                pn.z = u * k.z * vv.z;
                pn.w = u * k.w * vv.w;
                float4 po;
                if (c == 0) {
                    po.x = k.x * sc; po.y = k.y * sc;
                    po.z = k.z * sc; po.w = k.w * sc;
                } else {
                    po = __ldcg(O4 + e);
                }
                float d = fmaxf(fmaxf(fabsf(pn.x - po.x), fabsf(pn.y - po.y)),
                                fmaxf(fabsf(pn.z - po.z), fabsf(pn.w - po.w)));
                lm = fmaxf(lm, d);
                O4[e] = pn;
            }
#pragma unroll
            for (int o = 16; o; o >>= 1) lm = fmaxf(lm, __shfl_xor_sync(0xffffffffu, lm, o));
            if (lane == 0) s_red[wid] = lm;
            __syncthreads();
            if (wid == 0) {
                float t2 = (lane < NWB) ? s_red[lane] : 0.f;
#pragma unroll
                for (int o = 16; o; o >>= 1) t2 = fmaxf(t2, __shfl_xor_sync(0xffffffffu, t2, o));
                if (lane == 0) atomicMax(&g_maxdiff[c], __float_as_int(t2));
            }
        }
        int mdbits = lbar(&g_maxdiff[c]);
        if (__int_as_float(mdbits) < 1e-3f) return;   // converged forever
    }
}

extern "C" void kernel_launch(void* const* d_in, const int* in_sizes, int n_in,
                              void* d_out, int out_size) {
    const float* c1 = nullptr; const float* p1 = nullptr;
    const float* c2 = nullptr; const float* p2 = nullptr;
    for (int i = 0; i < n_in; ++i) {
        if (in_sizes[i] == BATCH * NPT * 2) {
            if (!c1) c1 = (const float*)d_in[i]; else c2 = (const float*)d_in[i];
        } else if (in_sizes[i] == BATCH * NPT) {
            if (!p1) p1 = (const float*)d_in[i]; else p2 = (const float*)d_in[i];
        }
    }
    sot_kernel<<<GRID, BLOCK>>>(c1, p1, c2, p2, (float*)d_out);
}

// round 3
// speedup vs baseline: 1.3981x; 1.2137x over previous
#include <cuda_runtime.h>
#include <math.h>
#include <float.h>

#define BATCH  8
#define NPT    1024
#define BN     8192           // BATCH * NPT
#define TOT    8388608        // BATCH * NPT * NPT
#define GRID   148
#define BLOCK  512
#define NWB    16             // warps per block
#define NTHR   (GRID*BLOCK)
#define MAXBLK 19             // max blocks per batch

// -------- persistent device state ----------------------------------------
__device__ __align__(16) float g_K[TOT];                  // K row-major [b][i][j]
__device__ __align__(16) float g_part[BATCH*MAXBLK*NPT];  // column partials
__device__ __align__(16) float g_a[BN];
__device__ __align__(16) float g_b[BN];
__device__ float g_sum[16];
__device__ int   g_maxM[BATCH];
__device__ int   g_bad;
__device__ int   g_maxdiff[10];
__device__ unsigned g_arr[GRID];      // all-thread barrier per-block counts
__device__ unsigned g_blkCnt;         // global barrier count
__device__ unsigned g_hvyCount;       // heavy barrier (monotonic across launches)
__device__ volatile unsigned g_hvyGen;

// -------- heavy barrier (setup only; may flush L1) ------------------------
__device__ __forceinline__ void heavy_barrier() {
    __threadfence();
    __syncthreads();
    if (threadIdx.x == 0) {
        unsigned g = g_hvyGen;
        unsigned t = atomicAdd(&g_hvyCount, 1u);
        if (t % (unsigned)GRID == (unsigned)(GRID - 1)) {
            __threadfence();
            g_hvyGen = g + 1u;
        } else {
            while (g_hvyGen == g) {}
        }
    }
    __syncthreads();
}

__device__ __forceinline__ void rel_inc(unsigned* p) {
    asm volatile("red.release.gpu.global.add.u32 [%0], %1;"
                 :: "l"(p), "r"(1u) : "memory");
}
__device__ __forceinline__ unsigned acq_ld(const unsigned* p) {
    unsigned v;
    asm volatile("ld.acquire.gpu.global.u32 %0, [%1];"
                 : "=r"(v) : "l"(p) : "memory");
    return v;
}

__global__ void __launch_bounds__(BLOCK, 1)
sot_kernel(const float* __restrict__ coord1, const float* __restrict__ prob1,
           const float* __restrict__ coord2, const float* __restrict__ prob2,
           float* __restrict__ Pout)
{
    const int tid  = threadIdx.x;
    const int bid  = blockIdx.x;
    const int gtid = bid * BLOCK + tid;
    const int lane = tid & 31;
    const int wid  = tid >> 5;

    __shared__ float s_u[2][64];
    __shared__ __align__(16) float s_v[2][NPT];
    __shared__ float s_red[NWB];
    __shared__ int   s_flag;
    __shared__ int   s_bad;

    // ---------------- Phase 0a: init + prob sums --------------------------
    if (gtid < GRID)                 g_arr[gtid] = 0;
    if (gtid == GRID)                g_blkCnt = 0;
    if (gtid >= 256 && gtid < 264)   g_maxM[gtid - 256] = 0;
    if (gtid == 264)                 g_bad = 0;
    if (gtid >= 272 && gtid < 282)   g_maxdiff[gtid - 272] = 0;
    if (tid == 0) s_bad = 0;

    if (bid < 16) {
        int b = bid & 7;
        const float* src = (bid < 8 ? prob1 : prob2) + (b << 10);
        float s = 0.f;
        for (int j = tid; j < NPT; j += BLOCK) s += src[j] + 1e-8f;
#pragma unroll
        for (int o = 16; o; o >>= 1) s += __shfl_xor_sync(0xffffffffu, s, o);
        if (lane == 0) s_red[wid] = s;
        __syncthreads();
        if (wid == 0) {
            float t = (lane < NWB) ? s_red[lane] : 0.f;
#pragma unroll
            for (int o = 16; o; o >>= 1) t += __shfl_xor_sync(0xffffffffu, t, o);
            if (lane == 0) g_sum[bid] = t;
        }
    }
    heavy_barrier();

    // ---------------- Phase 0b: a,b + per-batch max(M) --------------------
    for (int r = gtid; r < BN; r += NTHR) {
        int b = r >> 10;
        g_a[r] = (prob1[r] + 1e-8f) / g_sum[b];
        g_b[r] = (prob2[r] + 1e-8f) / g_sum[8 + b];
    }
    {
        int gw = gtid >> 5, nw = NTHR >> 5;
        for (int r = gw; r < BN; r += nw) {
            int b = r >> 10;
            float x0 = coord1[2 * r], x1 = coord1[2 * r + 1];
            const float2* y = (const float2*)(coord2 + (b << 11));
            float m = 0.f;
            for (int j = lane; j < NPT; j += 32) {
                float2 yy = y[j];
                float d0 = x0 - yy.x, d1 = x1 - yy.y;
                m = fmaxf(m, d0 * d0 + d1 * d1);
            }
#pragma unroll
            for (int o = 16; o; o >>= 1) m = fmaxf(m, __shfl_xor_sync(0xffffffffu, m, o));
            if (lane == 0) atomicMax(&g_maxM[b], __float_as_int(m));
        }
    }
    heavy_barrier();

    // ---------------- Phase 1: materialize K (row per block-pass) ---------
    for (int r = bid; r < BN; r += GRID) {
        int b = r >> 10, i = r & 1023;
        float invmax = 1.0f / __int_as_float(g_maxM[b]);
        const float2* cx = (const float2*)(coord1 + (b << 11));
        const float4* cy4 = (const float4*)(coord2 + (b << 11));
        float2 xi = cx[i];
        float4 yy = cy4[tid];                 // two points: (x0,y0,x1,y1)
        float d0 = xi.x - yy.x, d1 = xi.y - yy.y;
        float e0 = (d0 * d0 + d1 * d1) * invmax;
        float d2 = xi.x - yy.z, d3 = xi.y - yy.w;
        float e1 = (d2 * d2 + d3 * d3) * invmax;
        float2 k;
        k.x = expf(e0 * -10.0f);
        k.y = expf(e1 * -10.0f);
        ((float2*)(g_K + ((size_t)r << 10)))[tid] = k;
    }
    heavy_barrier();

    // ---------------- Phase 2: block->rows mapping -------------------------
    const int myb  = (bid * BATCH) / GRID;
    const int blk0 = (myb * GRID + BATCH - 1) / BATCH;
    const int blk1 = ((myb + 1) * GRID + BATCH - 1) / BATCH;
    const int nbb  = blk1 - blk0;
    const int lidx = bid - blk0;
    const int r_lo = (lidx * NPT) / nbb;
    const int r_hi = ((lidx + 1) * NPT) / nbb;
    const int nr   = r_hi - r_lo;

    const float*  Kb     = g_K + ((size_t)myb << 20);
    const float2* Krows2 = (const float2*)(Kb + ((size_t)r_lo << 10));
    float2*       pmine  = (float2*)(g_part + ((myb * MAXBLK + lidx) << 10));
    const float2* pbatch = (const float2*)(g_part + ((myb * MAXBLK) << 10));
    const float*  aB     = g_a + (myb << 10);
    const float2* bB2    = (const float2*)(g_b + (myb << 10));

    for (int i = tid; i < nr; i += BLOCK) s_u[0][i] = 1.0f / 1024.0f;
    __syncthreads();

    unsigned ph = 0, phA = 0;
    int par = 0;

    // barrier with all-thread release (publishes every thread's stores)
    auto lbar_all = [&]() {
        ph++; phA++;
        rel_inc(&g_arr[bid]);
        if (tid == 0) {
            while (acq_ld(&g_arr[bid]) < phA * (unsigned)BLOCK) {}
            rel_inc(&g_blkCnt);
            while (acq_ld(&g_blkCnt) < ph * (unsigned)GRID) {}
        }
        __syncthreads();
    };
    // barrier with tid0-only arrive; forwards s_bad / samples a flag.
    auto lbar_one = [&](const int* sample) -> int {
        ph++;
        __syncthreads();
        if (tid == 0) {
            if (s_bad) { atomicOr(&g_bad, 1); s_bad = 0; }
            rel_inc(&g_blkCnt);
            while (acq_ld(&g_blkCnt) < ph * (unsigned)GRID) {}
            s_flag = sample ? __ldcv(sample) : 0;
        }
        __syncthreads();
        return s_flag;
    };

    for (int c = 0; c < 10; ++c) {
        bool bad = false;
        for (int it = 0; it < 10; ++it) {
            // ---- Phase A: column partials  part_j = sum_i K_ij * u_i ------
            {
                float2 acc = make_float2(0.f, 0.f);
                const float2* bp = Krows2 + tid;
                int i = 0;
                for (; i + 4 <= nr; i += 4) {
                    float u0 = s_u[par][i],     u1 = s_u[par][i + 1];
                    float u2 = s_u[par][i + 2], u3 = s_u[par][i + 3];
                    float2 k0 = __ldg(bp + ((i    ) << 9));
                    float2 k1 = __ldg(bp + ((i + 1) << 9));
                    float2 k2 = __ldg(bp + ((i + 2) << 9));
                    float2 k3 = __ldg(bp + ((i + 3) << 9));
                    acc.x = fmaf(k0.x, u0, acc.x); acc.y = fmaf(k0.y, u0, acc.y);
                    acc.x = fmaf(k1.x, u1, acc.x); acc.y = fmaf(k1.y, u1, acc.y);
                    acc.x = fmaf(k2.x, u2, acc.x); acc.y = fmaf(k2.y, u2, acc.y);
                    acc.x = fmaf(k3.x, u3, acc.x); acc.y = fmaf(k3.y, u3, acc.y);
                }
                for (; i < nr; ++i) {
                    float u0 = s_u[par][i];
                    float2 k = __ldg(bp + (i << 9));
                    acc.x = fmaf(k.x, u0, acc.x); acc.y = fmaf(k.y, u0, acc.y);
                }
                pmine[tid] = acc;
            }
            lbar_all();

            // ---- Phase B: v = b/KtU (redundant per block, deterministic) --
            {
                float2 kt = make_float2(0.f, 0.f);
#pragma unroll 4
                for (int p = 0; p < nbb; ++p) {
                    float2 x = __ldcg(pbatch + (p << 9) + tid);
                    kt.x += x.x; kt.y += x.y;
                }
                float2 bb = __ldg(bB2 + tid);
                float vx = bb.x / kt.x;
                float vy = bb.y / kt.y;
                if (kt.x == 0.f || kt.y == 0.f ||
                    !(fabsf(vx) <= FLT_MAX) || !(fabsf(vy) <= FLT_MAX))
                    s_bad = 1;
                s_v[par ^ 1][2 * tid]     = vx;
                s_v[par ^ 1][2 * tid + 1] = vy;
            }
            __syncthreads();

            // ---- u-pass: u_i = a_i / dot(K_row_i, v) ----------------------
            {
                float4 vr[8];
                const float4* v4 = (const float4*)s_v[par ^ 1];
#pragma unroll
                for (int s = 0; s < 8; ++s) vr[s] = v4[lane + 32 * s];
                for (int r = wid; r < nr; r += NWB) {
                    const float4* m4 = (const float4*)(Kb + ((size_t)(r_lo + r) << 10));
                    float a0 = 0.f, a1 = 0.f;
#pragma unroll
                    for (int s = 0; s < 8; s += 2) {
                        float4 k0 = __ldg(m4 + lane + 32 * s);
                        float4 k1 = __ldg(m4 + lane + 32 * (s + 1));
                        a0 = fmaf(k0.x, vr[s].x, fmaf(k0.y, vr[s].y,
                             fmaf(k0.z, vr[s].z, fmaf(k0.w, vr[s].w, a0))));
                        a1 = fmaf(k1.x, vr[s+1].x, fmaf(k1.y, vr[s+1].y,
                             fmaf(k1.z, vr[s+1].z, fmaf(k1.w, vr[s+1].w, a1))));
                    }
                    float acc = a0 + a1;
#pragma unroll
                    for (int o = 16; o; o >>= 1) acc += __shfl_xor_sync(0xffffffffu, acc, o);
                    if (lane == 0) {
                        float uu = __ldg(aB + r_lo + r) / acc;
                        if (acc == 0.f || !(fabsf(uu) <= FLT_MAX)) s_bad = 1;
                        s_u[par ^ 1][r] = uu;
                    }
                }
            }
            if (lbar_one(&g_bad)) { bad = true; break; }
            par ^= 1;   // commit
        }

        if (bad) {
            if (c == 0) {   // P never updated: P0 = K / 2^20 (my rows)
                const float4* K4 = (const float4*)(Kb + ((size_t)r_lo << 10));
                float4* O4 = (float4*)(Pout + ((size_t)myb << 20) + ((size_t)r_lo << 10));
                const float sc = 1.0f / 1048576.0f;
                int n4 = nr << 8;
                for (int e = tid; e < n4; e += BLOCK) {
                    float4 k = __ldg(K4 + e);
                    O4[e] = make_float4(k.x * sc, k.y * sc, k.z * sc, k.w * sc);
                }
            }
            return;
        }

        // ---- P phase: Pn = u * K * v^T (my rows) + maxdiff ----------------
        {
            const float sc = 1.0f / 1048576.0f;
            const float4* v4 = (const float4*)s_v[par];
            float lm = 0.f;
            for (int r = wid; r < nr; r += NWB) {
                float u = s_u[par][r];
                const float4* k4 = (const float4*)(Kb + ((size_t)(r_lo + r) << 10));
                float4* o4 = (float4*)(Pout + ((size_t)myb << 20) + ((size_t)(r_lo + r) << 10));
#pragma unroll
                for (int s = 0; s < 8; ++s) {
                    float4 k  = __ldg(k4 + lane + 32 * s);
                    float4 vv = v4[lane + 32 * s];
                    float4 pn;
                    pn.x = u * k.x * vv.x;  pn.y = u * k.y * vv.y;
                    pn.z = u * k.z * vv.z;  pn.w = u * k.w * vv.w;
                    float4 po;
                    if (c == 0) {
                        po.x = k.x * sc; po.y = k.y * sc;
                        po.z = k.z * sc; po.w = k.w * sc;
                    } else {
                        po = __ldcg(o4 + lane + 32 * s);
                    }
                    float d = fmaxf(fmaxf(fabsf(pn.x - po.x), fabsf(pn.y - po.y)),
                                    fmaxf(fabsf(pn.z - po.z), fabsf(pn.w - po.w)));
                    lm = fmaxf(lm, d);
                    o4[lane + 32 * s] = pn;
                }
            }
#pragma unroll
            for (int o = 16; o; o >>= 1) lm = fmaxf(lm, __shfl_xor_sync(0xffffffffu, lm, o));
            if (lane == 0) s_red[wid] = lm;
            __syncthreads();
            if (wid == 0) {
                float t2 = (lane < NWB) ? s_red[lane] : 0.f;
#pragma unroll
                for (int o = 16; o; o >>= 1) t2 = fmaxf(t2, __shfl_xor_sync(0xffffffffu, t2, o));
                if (lane == 0) atomicMax(&g_maxdiff[c], __float_as_int(t2));
            }
        }
        int mdbits = lbar_one(&g_maxdiff[c]);   // tid0's release orders its atomicMax
        if (__int_as_float(mdbits) < 1e-3f) return;
    }
}

extern "C" void kernel_launch(void* const* d_in, const int* in_sizes, int n_in,
                              void* d_out, int out_size) {
    const float* c1 = nullptr; const float* p1 = nullptr;
    const float* c2 = nullptr; const float* p2 = nullptr;
    for (int i = 0; i < n_in; ++i) {
        if (in_sizes[i] == BATCH * NPT * 2) {
            if (!c1) c1 = (const float*)d_in[i]; else c2 = (const float*)d_in[i];
        } else if (in_sizes[i] == BATCH * NPT) {
            if (!p1) p1 = (const float*)d_in[i]; else p2 = (const float*)d_in[i];
        }
    }
    sot_kernel<<<GRID, BLOCK>>>(c1, p1, c2, p2, (float*)d_out);
}

// round 4
// speedup vs baseline: 1.9548x; 1.3982x over previous
#include <cuda_runtime.h>
#include <math.h>
#include <float.h>

#define BATCH  8
#define NPT    1024
#define BN     8192
#define TOT    8388608        // BATCH*NPT*NPT
#define BLOCK  512
#define NWB    16             // warps per block
#define MAXG   152            // max grid (GB300 SM count)
#define MAXBLK 19             // max blocks per batch

// -------- persistent device state (reset each launch) ---------------------
__device__ __align__(16) float g_K[TOT];                   // K [b][i][j]
__device__ __align__(16) float g_part[BATCH*MAXBLK*NPT];   // column partials
__device__ int g_maxM[BATCH];
__device__ int g_bad;
__device__ int g_maxdiff[10];
__device__ unsigned g_warpArr[MAXG];   // per-block warp arrivals (light bars)
__device__ unsigned g_batCnt[BATCH];   // per-batch barrier counter
__device__ unsigned g_blkCnt;          // global barrier counter
__device__ unsigned g_hvyCount;        // heavy barrier: monotonic across launches
__device__ volatile unsigned g_hvyGen;

__device__ __forceinline__ void heavy_barrier(int nb) {
    __threadfence();
    __syncthreads();
    if (threadIdx.x == 0) {
        unsigned g = g_hvyGen;
        unsigned t = atomicAdd(&g_hvyCount, 1u);
        if (t % (unsigned)nb == (unsigned)(nb - 1)) {
            __threadfence();
            g_hvyGen = g + 1u;
        } else {
            while (g_hvyGen == g) {}
        }
    }
    __syncthreads();
}

__device__ __forceinline__ void rel_inc(unsigned* p) {
    asm volatile("red.release.gpu.global.add.u32 [%0], %1;"
                 :: "l"(p), "r"(1u) : "memory");
}
__device__ __forceinline__ unsigned acq_ld(const unsigned* p) {
    unsigned v;
    asm volatile("ld.acquire.gpu.global.u32 %0, [%1];"
                 : "=r"(v) : "l"(p) : "memory");
    return v;
}

__global__ void __launch_bounds__(BLOCK, 1)
sot_kernel(const float* __restrict__ coord1, const float* __restrict__ prob1,
           const float* __restrict__ coord2, const float* __restrict__ prob2,
           float* __restrict__ Pout)
{
    const int tid  = threadIdx.x;
    const int bid  = blockIdx.x;
    const int nb   = gridDim.x;
    const int lane = tid & 31;
    const int wid  = tid >> 5;

    // block -> batch/rows mapping
    const int myb  = (bid * BATCH) / nb;
    const int blk0 = (myb * nb + BATCH - 1) / BATCH;
    const int blk1 = ((myb + 1) * nb + BATCH - 1) / BATCH;
    const int nbb  = blk1 - blk0;
    const int lidx = bid - blk0;
    const int r_lo = (lidx * NPT) / nbb;
    const int r_hi = ((lidx + 1) * NPT) / nbb;
    const int nr   = r_hi - r_lo;

    __shared__ __align__(16) float s_v[2][NPT];   // 8KB  (cur / prev chunk)
    __shared__ float s_u[2][64];
    __shared__ __align__(16) float s_b[NPT];      // 4KB
    __shared__ float s_a[64];
    __shared__ float2 s_xi[64];
    __shared__ float s_red[NWB];
    __shared__ float s_suma, s_sumb;
    __shared__ int   s_bad, s_f0, s_f1;

    const float*  Kb     = g_K + ((size_t)myb << 20);
    const float2* Krows2 = (const float2*)(Kb + ((size_t)r_lo << 10));
    float2*       pmine  = (float2*)(g_part + ((myb * MAXBLK + lidx) << 10));
    const float2* pbatch = (const float2*)(g_part + ((myb * MAXBLK) << 10));

    // ------------- resets (protected by heavy barrier below) ---------------
    if (tid == 0) { g_warpArr[bid] = 0; s_bad = 0; }
    if (bid == 0) {
        if (tid == 1)                g_blkCnt = 0;
        if (tid == 2)                g_bad = 0;
        if (tid == 3)                g_maxM[0] = 0;   // maxM reset spread
        if (tid >= 8  && tid < 16)   g_batCnt[tid - 8] = 0;
        if (tid >= 16 && tid < 26)   g_maxdiff[tid - 16] = 0;
        if (tid >= 32 && tid < 39)   g_maxM[tid - 31] = 0;
    }

    // ------------- block-local: prob sums (redundant), a, b, coords --------
    const float*  p1b  = prob1 + (myb << 10);
    const float2* p2b2 = (const float2*)(prob2 + (myb << 10));
    {
        const float2* p1b2 = (const float2*)p1b;
        float2 x1 = p1b2[tid];
        float2 x2 = p2b2[tid];
        float sa = (x1.x + 1e-8f) + (x1.y + 1e-8f);
        float sb = (x2.x + 1e-8f) + (x2.y + 1e-8f);
#pragma unroll
        for (int o = 16; o; o >>= 1) {
            sa += __shfl_xor_sync(0xffffffffu, sa, o);
            sb += __shfl_xor_sync(0xffffffffu, sb, o);
        }
        if (lane == 0) s_red[wid] = sa;
        __syncthreads();
        if (wid == 0) {
            float t = (lane < NWB) ? s_red[lane] : 0.f;
#pragma unroll
            for (int o = 16; o; o >>= 1) t += __shfl_xor_sync(0xffffffffu, t, o);
            if (lane == 0) s_suma = t;
        }
        __syncthreads();
        if (lane == 0) s_red[wid] = sb;
        __syncthreads();
        if (wid == 0) {
            float t = (lane < NWB) ? s_red[lane] : 0.f;
#pragma unroll
            for (int o = 16; o; o >>= 1) t += __shfl_xor_sync(0xffffffffu, t, o);
            if (lane == 0) s_sumb = t;
        }
        __syncthreads();
    }
    {
        float2 x2 = p2b2[tid];
        ((float2*)s_b)[tid] = make_float2((x2.x + 1e-8f) / s_sumb,
                                          (x2.y + 1e-8f) / s_sumb);
        if (tid < nr) {
            s_a[tid]  = (p1b[r_lo + tid] + 1e-8f) / s_suma;
            s_xi[tid] = ((const float2*)(coord1 + (myb << 11)))[r_lo + tid];
        }
        // prev-chunk buffers preloaded with uniform u0,v0 (chunk-0 compare = P0)
        ((float2*)s_v[1])[tid] = make_float2(1.0f/1024.0f, 1.0f/1024.0f);
        if (tid < 64) s_u[1][tid] = 1.0f/1024.0f;
    }
    heavy_barrier(nb);

    // ------------- light barriers ------------------------------------------
    unsigned phW = 0, phB = 0, phG = 0;
    auto batch_bar = [&]() {
        phW++; phB++;
        __syncwarp();
        if (lane == 0) rel_inc(&g_warpArr[bid]);
        if (tid == 0) {
            while (acq_ld(&g_warpArr[bid]) < phW * (unsigned)NWB) {}
            rel_inc(&g_batCnt[myb]);
            while (acq_ld(&g_batCnt[myb]) < phB * (unsigned)nbb) {}
        }
        __syncthreads();
    };
    auto global_bar = [&]() {
        phW++; phG++;
        __syncwarp();
        if (lane == 0) rel_inc(&g_warpArr[bid]);
        if (tid == 0) {
            while (acq_ld(&g_warpArr[bid]) < phW * (unsigned)NWB) {}
            rel_inc(&g_blkCnt);
            while (acq_ld(&g_blkCnt) < phG * (unsigned)nb) {}
        }
        __syncthreads();
    };

    // ------------- maxM: own rows share + atomicMax + batch barrier --------
    {
        const float2* cy = (const float2*)(coord2 + (myb << 11));
        float m = 0.f;
        for (int r = wid; r < nr; r += NWB) {
            float2 xi = s_xi[r];
            for (int j = lane; j < NPT; j += 32) {
                float2 yy = cy[j];
                float d0 = xi.x - yy.x, d1 = xi.y - yy.y;
                m = fmaxf(m, d0 * d0 + d1 * d1);
            }
        }
#pragma unroll
        for (int o = 16; o; o >>= 1) m = fmaxf(m, __shfl_xor_sync(0xffffffffu, m, o));
        if (lane == 0) s_red[wid] = m;
        __syncthreads();
        if (wid == 0) {
            float t = (lane < NWB) ? s_red[lane] : 0.f;
#pragma unroll
            for (int o = 16; o; o >>= 1) t = fmaxf(t, __shfl_xor_sync(0xffffffffu, t, o));
            if (lane == 0 && tid == 0) atomicMax(&g_maxM[myb], __float_as_int(t));
        }
    }
    batch_bar();

    // ------------- K materialization fused with initial partials -----------
    {
        int mb;
        asm volatile("ld.global.cg.b32 %0, [%1];" : "=r"(mb) : "l"(&g_maxM[myb]));
        float nscale = -10.0f / __int_as_float(mb);
        const float4* cy4 = (const float4*)(coord2 + (myb << 11));
        float4 yy = cy4[tid];               // cols 2tid, 2tid+1
        float2 acc = make_float2(0.f, 0.f);
        float2* Krow = (float2*)(Kb + ((size_t)r_lo << 10)) + tid;
        for (int r = 0; r < nr; ++r) {
            float2 xi = s_xi[r];
            float d0 = xi.x - yy.x, d1 = xi.y - yy.y;
            float d2 = xi.x - yy.z, d3 = xi.y - yy.w;
            float2 k;
            k.x = __expf((d0 * d0 + d1 * d1) * nscale);
            k.y = __expf((d2 * d2 + d3 * d3) * nscale);
            Krow[(size_t)r << 9] = k;
            acc.x += k.x; acc.y += k.y;
        }
        pmine[tid] = make_float2(acc.x * (1.0f/1024.0f), acc.y * (1.0f/1024.0f));
    }

    // ------------- A-pass lambda: partials from current u ------------------
    auto do_A = [&](int cp) {
        float2 acc = make_float2(0.f, 0.f);
        const float2* bp = Krows2 + tid;
        int i = 0;
        for (; i + 4 <= nr; i += 4) {
            float u0 = s_u[cp][i],     u1 = s_u[cp][i + 1];
            float u2 = s_u[cp][i + 2], u3 = s_u[cp][i + 3];
            float2 k0 = __ldg(bp + ((size_t)(i    ) << 9));
            float2 k1 = __ldg(bp + ((size_t)(i + 1) << 9));
            float2 k2 = __ldg(bp + ((size_t)(i + 2) << 9));
            float2 k3 = __ldg(bp + ((size_t)(i + 3) << 9));
            acc.x = fmaf(k0.x, u0, acc.x); acc.y = fmaf(k0.y, u0, acc.y);
            acc.x = fmaf(k1.x, u1, acc.x); acc.y = fmaf(k1.y, u1, acc.y);
            acc.x = fmaf(k2.x, u2, acc.x); acc.y = fmaf(k2.y, u2, acc.y);
            acc.x = fmaf(k3.x, u3, acc.x); acc.y = fmaf(k3.y, u3, acc.y);
        }
        for (; i < nr; ++i) {
            float u0 = s_u[cp][i];
            float2 k = __ldg(bp + ((size_t)i << 9));
            acc.x = fmaf(k.x, u0, acc.x); acc.y = fmaf(k.y, u0, acc.y);
        }
        pmine[tid] = acc;
    };

    // ------------- final-output lambda -------------------------------------
    auto write_final = [&](int buf) {
        const float4* v4 = (const float4*)s_v[buf];
        for (int r = wid; r < nr; r += NWB) {
            float u = s_u[buf][r];
            const float4* k4 = (const float4*)(Kb + ((size_t)(r_lo + r) << 10));
            float4* o4 = (float4*)(Pout + ((size_t)myb << 20) + ((size_t)(r_lo + r) << 10));
#pragma unroll
            for (int s = 0; s < 8; ++s) {
                float4 k  = __ldg(k4 + lane + 32 * s);
                float4 vv = v4[lane + 32 * s];
                float4 pn;
                pn.x = (u * k.x) * vv.x;  pn.y = (u * k.y) * vv.y;
                pn.z = (u * k.z) * vv.z;  pn.w = (u * k.w) * vv.w;
                __stcs(o4 + lane + 32 * s, pn);
            }
        }
    };

    // ------------- Sinkhorn chunks -----------------------------------------
    for (int c = 0; c < 10; ++c) {
        const int cp = c & 1;
        for (int it = 0; it < 10; ++it) {
            batch_bar();                         // partials of all batch blocks
            // ---- B: v = b / sum(partials) -------------------------------
            {
                float2 kt = make_float2(0.f, 0.f);
#pragma unroll 4
                for (int p = 0; p < nbb; ++p) {
                    float2 x = __ldcg(pbatch + (p << 9) + tid);
                    kt.x += x.x; kt.y += x.y;
                }
                float2 bb = ((const float2*)s_b)[tid];
                float vx = bb.x / kt.x;
                float vy = bb.y / kt.y;
                if (kt.x == 0.f || kt.y == 0.f ||
                    !(fabsf(vx) <= FLT_MAX) || !(fabsf(vy) <= FLT_MAX))
                    s_bad = 1;
                ((float2*)s_v[cp])[tid] = make_float2(vx, vy);
            }
            __syncthreads();
            // ---- u-pass: u_i = a_i / dot(K_row_i, v) --------------------
            {
                float4 vr[8];
                const float4* v4 = (const float4*)s_v[cp];
#pragma unroll
                for (int s = 0; s < 8; ++s) vr[s] = v4[lane + 32 * s];
                for (int r = wid; r < nr; r += NWB) {
                    const float4* m4 = (const float4*)(Kb + ((size_t)(r_lo + r) << 10));
                    float a0 = 0.f, a1 = 0.f;
#pragma unroll
                    for (int s = 0; s < 8; s += 2) {
                        float4 k0 = __ldg(m4 + lane + 32 * s);
                        float4 k1 = __ldg(m4 + lane + 32 * (s + 1));
                        a0 = fmaf(k0.x, vr[s].x, fmaf(k0.y, vr[s].y,
                             fmaf(k0.z, vr[s].z, fmaf(k0.w, vr[s].w, a0))));
                        a1 = fmaf(k1.x, vr[s+1].x, fmaf(k1.y, vr[s+1].y,
                             fmaf(k1.z, vr[s+1].z, fmaf(k1.w, vr[s+1].w, a1))));
                    }
                    float acc = a0 + a1;
#pragma unroll
                    for (int o = 16; o; o >>= 1) acc += __shfl_xor_sync(0xffffffffu, acc, o);
                    if (lane == 0) {
                        float uu = s_a[r] / acc;
                        if (acc == 0.f || !(fabsf(uu) <= FLT_MAX)) s_bad = 1;
                        s_u[cp][r] = uu;
                    }
                }
            }
            __syncthreads();
            if (it < 9) do_A(cp);                // partials for next iteration
        }

        // ---- chunk check: maxdiff without materializing P -----------------
        {
            const float4* v4c = (const float4*)s_v[cp];
            const float4* v4p = (const float4*)s_v[cp ^ 1];
            float lm = 0.f;
            for (int r = wid; r < nr; r += NWB) {
                float u  = s_u[cp][r];
                float up = s_u[cp ^ 1][r];
                const float4* k4 = (const float4*)(Kb + ((size_t)(r_lo + r) << 10));
#pragma unroll
                for (int s = 0; s < 8; ++s) {
                    float4 k  = __ldg(k4 + lane + 32 * s);
                    float4 vv = v4c[lane + 32 * s];
                    float4 vp = v4p[lane + 32 * s];
                    float dx = fabsf((u * k.x) * vv.x - (up * k.x) * vp.x);
                    float dy = fabsf((u * k.y) * vv.y - (up * k.y) * vp.y);
                    float dz = fabsf((u * k.z) * vv.z - (up * k.z) * vp.z);
                    float dw = fabsf((u * k.w) * vv.w - (up * k.w) * vp.w);
                    lm = fmaxf(lm, fmaxf(fmaxf(dx, dy), fmaxf(dz, dw)));
                }
            }
#pragma unroll
            for (int o = 16; o; o >>= 1) lm = fmaxf(lm, __shfl_xor_sync(0xffffffffu, lm, o));
            if (lane == 0) s_red[wid] = lm;
            __syncthreads();
            if (wid == 0) {
                float t = (lane < NWB) ? s_red[lane] : 0.f;
#pragma unroll
                for (int o = 16; o; o >>= 1) t = fmaxf(t, __shfl_xor_sync(0xffffffffu, t, o));
                if (lane == 0 && tid == 0) {
                    atomicMax(&g_maxdiff[c], __float_as_int(t));
                    if (s_bad) { atomicOr(&g_bad, 1); s_bad = 0; }
                }
            }
        }
        global_bar();                            // tid0's release orders atomics
        if (tid == 0) {
            int f0, f1;
            asm volatile("ld.global.cg.b32 %0, [%1];" : "=r"(f0) : "l"(&g_bad));
            asm volatile("ld.global.cg.b32 %0, [%1];" : "=r"(f1) : "l"(&g_maxdiff[c]));
            s_f0 = f0; s_f1 = f1;
        }
        __syncthreads();
        if (s_f0) {                              // bad: output previous chunk's P
            write_final(cp ^ 1);                 // (chunk 0: prev = uniform = P0)
            return;
        }
        if (__int_as_float(s_f1) < 1e-3f || c == 9) {
            write_final(cp);                     // converged (or exhausted)
            return;
        }
        do_A(cp);                                // partials for next chunk's it0
    }
}

extern "C" void kernel_launch(void* const* d_in, const int* in_sizes, int n_in,
                              void* d_out, int out_size) {
    static int nsm = 0;
    if (nsm == 0) {
        int dev = 0; cudaGetDevice(&dev);
        int v = 0;
        if (cudaDeviceGetAttribute(&v, cudaDevAttrMultiProcessorCount, dev)
                != cudaSuccess || v <= 0) v = 148;
        if (v > MAXG) v = MAXG;
        if (v < BATCH) v = BATCH;
        nsm = v;
    }
    const float* c1 = nullptr; const float* p1 = nullptr;
    const float* c2 = nullptr; const float* p2 = nullptr;
    for (int i = 0; i < n_in; ++i) {
        if (in_sizes[i] == BATCH * NPT * 2) {
            if (!c1) c1 = (const float*)d_in[i]; else c2 = (const float*)d_in[i];
        } else if (in_sizes[i] == BATCH * NPT) {
            if (!p1) p1 = (const float*)d_in[i]; else p2 = (const float*)d_in[i];
        }
    }
    sot_kernel<<<nsm, BLOCK>>>(c1, p1, c2, p2, (float*)d_out);
}

// round 5
// speedup vs baseline: 2.7637x; 1.4138x over previous
#include <cuda_runtime.h>
#include <cuda_fp16.h>
#include <math.h>
#include <float.h>

#define BATCH  8
#define NPT    1024
#define TOT    8388608        // BATCH*NPT*NPT
#define BLOCK  512
#define NWB    16             // warps per block
#define MAXG   152
#define MAXBLK 19
#define PARTN  (BATCH*MAXBLK*NPT)

// -------- persistent device state (reset each launch) ---------------------
__device__ __align__(16) __half g_Kh[TOT];       // K in fp16 [b][i][j]
__device__ __align__(16) float  g_part[2][PARTN];// double-buffered partials
__device__ int g_maxM[BATCH];
__device__ int g_bad;
__device__ int g_maxdiff[10];
__device__ unsigned g_batCnt[BATCH];
__device__ unsigned g_blkCnt;
__device__ unsigned g_hvyCount;                  // monotonic across launches
__device__ volatile unsigned g_hvyGen;

__device__ __forceinline__ void heavy_barrier(int nb) {
    __threadfence();
    __syncthreads();
    if (threadIdx.x == 0) {
        unsigned g = g_hvyGen;
        unsigned t = atomicAdd(&g_hvyCount, 1u);
        if (t % (unsigned)nb == (unsigned)(nb - 1)) {
            __threadfence();
            g_hvyGen = g + 1u;
        } else {
            while (g_hvyGen == g) {}
        }
    }
    __syncthreads();
}

__device__ __forceinline__ void rel_inc(unsigned* p) {
    asm volatile("red.release.gpu.global.add.u32 [%0], %1;"
                 :: "l"(p), "r"(1u) : "memory");
}
__device__ __forceinline__ unsigned acq_ld(const unsigned* p) {
    unsigned v;
    asm volatile("ld.acquire.gpu.global.u32 %0, [%1];"
                 : "=r"(v) : "l"(p) : "memory");
    return v;
}
__device__ __forceinline__ int ld_cg_i(const int* p) {
    int v;
    asm volatile("ld.global.cg.b32 %0, [%1];" : "=r"(v) : "l"(p) : "memory");
    return v;
}
__device__ __forceinline__ float2 h2f(unsigned q) {
    __half2 h = *reinterpret_cast<__half2*>(&q);
    return __half22float2(h);
}

__global__ void __launch_bounds__(BLOCK, 1)
sot_kernel(const float* __restrict__ coord1, const float* __restrict__ prob1,
           const float* __restrict__ coord2, const float* __restrict__ prob2,
           float* __restrict__ Pout)
{
    const int tid  = threadIdx.x;
    const int bid  = blockIdx.x;
    const int nb   = gridDim.x;
    const int lane = tid & 31;
    const int wid  = tid >> 5;

    const int myb  = (bid * BATCH) / nb;
    const int blk0 = (myb * nb + BATCH - 1) / BATCH;
    const int blk1 = ((myb + 1) * nb + BATCH - 1) / BATCH;
    const int nbb  = blk1 - blk0;
    const int lidx = bid - blk0;
    const int r_lo = (lidx * NPT) / nbb;
    const int r_hi = ((lidx + 1) * NPT) / nbb;
    const int nr   = r_hi - r_lo;

    __shared__ __align__(16) float s_v[2][NPT];
    __shared__ float s_u[2][64];
    __shared__ __align__(16) float s_b[NPT];
    __shared__ float s_a[64];
    __shared__ float2 s_xi[64];
    __shared__ float s_red[NWB];
    __shared__ float s_suma, s_sumb;
    __shared__ int   s_bad, s_f0, s_f1;

    __half* Kbh = g_Kh + ((size_t)myb << 20);

    // ---------------- resets ----------------------------------------------
    if (tid == 0) s_bad = 0;
    if (bid == 0) {
        if (tid == 1)               g_blkCnt = 0;
        if (tid == 2)               g_bad = 0;
        if (tid >= 8  && tid < 16)  g_batCnt[tid - 8] = 0;
        if (tid >= 16 && tid < 26)  g_maxdiff[tid - 16] = 0;
        if (tid >= 32 && tid < 40)  g_maxM[tid - 32] = 0;
    }

    // ---------------- block-local prob sums, a, b, coords -----------------
    const float*  p1b  = prob1 + (myb << 10);
    const float2* p2b2 = (const float2*)(prob2 + (myb << 10));
    {
        const float2* p1b2 = (const float2*)p1b;
        float2 x1 = p1b2[tid];
        float2 x2 = p2b2[tid];
        float sa = (x1.x + 1e-8f) + (x1.y + 1e-8f);
        float sb = (x2.x + 1e-8f) + (x2.y + 1e-8f);
#pragma unroll
        for (int o = 16; o; o >>= 1) {
            sa += __shfl_xor_sync(0xffffffffu, sa, o);
            sb += __shfl_xor_sync(0xffffffffu, sb, o);
        }
        if (lane == 0) s_red[wid] = sa;
        __syncthreads();
        if (wid == 0) {
            float t = (lane < NWB) ? s_red[lane] : 0.f;
#pragma unroll
            for (int o = 16; o; o >>= 1) t += __shfl_xor_sync(0xffffffffu, t, o);
            if (lane == 0) s_suma = t;
        }
        __syncthreads();
        if (lane == 0) s_red[wid] = sb;
        __syncthreads();
        if (wid == 0) {
            float t = (lane < NWB) ? s_red[lane] : 0.f;
#pragma unroll
            for (int o = 16; o; o >>= 1) t += __shfl_xor_sync(0xffffffffu, t, o);
            if (lane == 0) s_sumb = t;
        }
        __syncthreads();
    }
    {
        float2 x2 = p2b2[tid];
        ((float2*)s_b)[tid] = make_float2((x2.x + 1e-8f) / s_sumb,
                                          (x2.y + 1e-8f) / s_sumb);
        if (tid < nr) {
            s_a[tid]  = (p1b[r_lo + tid] + 1e-8f) / s_suma;
            s_xi[tid] = ((const float2*)(coord1 + (myb << 11)))[r_lo + tid];
        }
        ((float2*)s_v[1])[tid] = make_float2(1.0f/1024.0f, 1.0f/1024.0f);
        if (tid < 64) s_u[1][tid] = 1.0f/1024.0f;
    }
    heavy_barrier(nb);

    // ---------------- light barriers (cg::grid_sync pattern) ---------------
    unsigned phB = 0, phG = 0;
    auto batch_bar = [&]() {
        phB++;
        __syncthreads();
        if (tid == 0) {
            rel_inc(&g_batCnt[myb]);
            while (acq_ld(&g_batCnt[myb]) < phB * (unsigned)nbb) {}
        }
        __syncthreads();
    };
    auto global_bar = [&]() {
        phG++;
        __syncthreads();
        if (tid == 0) {
            if (s_bad) { atomicOr(&g_bad, 1); s_bad = 0; }
            rel_inc(&g_blkCnt);
            while (acq_ld(&g_blkCnt) < phG * (unsigned)nb) {}
        }
        __syncthreads();
    };

    // ---------------- maxM over own rows ----------------------------------
    {
        const float2* cy = (const float2*)(coord2 + (myb << 11));
        float m = 0.f;
        for (int r = wid; r < nr; r += NWB) {
            float2 xi = s_xi[r];
            for (int j = lane; j < NPT; j += 32) {
                float2 yy = cy[j];
                float d0 = xi.x - yy.x, d1 = xi.y - yy.y;
                m = fmaxf(m, d0 * d0 + d1 * d1);
            }
        }
#pragma unroll
        for (int o = 16; o; o >>= 1) m = fmaxf(m, __shfl_xor_sync(0xffffffffu, m, o));
        if (lane == 0) s_red[wid] = m;
        __syncthreads();
        if (wid == 0) {
            float t = (lane < NWB) ? s_red[lane] : 0.f;
#pragma unroll
            for (int o = 16; o; o >>= 1) t = fmaxf(t, __shfl_xor_sync(0xffffffffu, t, o));
            if (lane == 0 && tid == 0) atomicMax(&g_maxM[myb], __float_as_int(t));
        }
    }
    batch_bar();

    // ---------------- K materialization (fp16) + initial partials ----------
    {
        float nscale = -10.0f / __int_as_float(ld_cg_i(&g_maxM[myb]));
        const float4* cy4 = (const float4*)(coord2 + (myb << 11));
        float4 yy = cy4[tid];                 // cols 2tid, 2tid+1
        float2 acc = make_float2(0.f, 0.f);
        __half2* Krow = (__half2*)(Kbh + ((size_t)r_lo << 10)) + tid;
        for (int r = 0; r < nr; ++r) {
            float2 xi = s_xi[r];
            float d0 = xi.x - yy.x, d1 = xi.y - yy.y;
            float d2 = xi.x - yy.z, d3 = xi.y - yy.w;
            float kx = __expf((d0 * d0 + d1 * d1) * nscale);
            float ky = __expf((d2 * d2 + d3 * d3) * nscale);
            __half2 h = __floats2half2_rn(kx, ky);
            Krow[(size_t)r << 9] = h;
            float2 f = __half22float2(h);     // rounded values for consistency
            acc.x += f.x; acc.y += f.y;
        }
        float2* pm0 = (float2*)(g_part[0] + ((myb * MAXBLK + lidx) << 10));
        pm0[tid] = make_float2(acc.x * (1.0f/1024.0f), acc.y * (1.0f/1024.0f));
    }

    // ---------------- A-pass: column partials from current u ---------------
    auto do_A = [&](int cp, int par) {
        const unsigned* bp = (const unsigned*)(Kbh + ((size_t)r_lo << 10)) + tid;
        float2 acc = make_float2(0.f, 0.f);
        int i = 0;
        for (; i + 4 <= nr; i += 4) {
            float u0 = s_u[cp][i],     u1 = s_u[cp][i + 1];
            float u2 = s_u[cp][i + 2], u3 = s_u[cp][i + 3];
            unsigned q0 = __ldg(bp + ((size_t)(i    ) << 9));
            unsigned q1 = __ldg(bp + ((size_t)(i + 1) << 9));
            unsigned q2 = __ldg(bp + ((size_t)(i + 2) << 9));
            unsigned q3 = __ldg(bp + ((size_t)(i + 3) << 9));
            float2 f0 = h2f(q0), f1 = h2f(q1), f2 = h2f(q2), f3 = h2f(q3);
            acc.x = fmaf(f0.x, u0, acc.x); acc.y = fmaf(f0.y, u0, acc.y);
            acc.x = fmaf(f1.x, u1, acc.x); acc.y = fmaf(f1.y, u1, acc.y);
            acc.x = fmaf(f2.x, u2, acc.x); acc.y = fmaf(f2.y, u2, acc.y);
            acc.x = fmaf(f3.x, u3, acc.x); acc.y = fmaf(f3.y, u3, acc.y);
        }
        for (; i < nr; ++i) {
            float u0 = s_u[cp][i];
            float2 f = h2f(__ldg(bp + ((size_t)i << 9)));
            acc.x = fmaf(f.x, u0, acc.x); acc.y = fmaf(f.y, u0, acc.y);
        }
        float2* pd = (float2*)(g_part[par] + ((myb * MAXBLK + lidx) << 10));
        pd[tid] = acc;
    };

    // ---------------- final output ----------------------------------------
    auto write_final = [&](int buf) {
        const float4* v4 = (const float4*)s_v[buf];
        for (int r = wid; r < nr; r += NWB) {
            float u = s_u[buf][r];
            const uint2* k2 = (const uint2*)(Kbh + ((size_t)(r_lo + r) << 10));
            float4* o4 = (float4*)(Pout + ((size_t)myb << 20) + ((size_t)(r_lo + r) << 10));
#pragma unroll
            for (int c = 0; c < 8; ++c) {
                uint2 q = __ldg(k2 + lane + 32 * c);
                float2 f0 = h2f(q.x), f1 = h2f(q.y);
                float4 vv = v4[lane + 32 * c];
                float4 pn;
                pn.x = (u * f0.x) * vv.x;  pn.y = (u * f0.y) * vv.y;
                pn.z = (u * f1.x) * vv.z;  pn.w = (u * f1.y) * vv.w;
                __stcs(o4 + lane + 32 * c, pn);
            }
        }
    };

    // ---------------- Sinkhorn chunks --------------------------------------
    int parity = 0;
    for (int c = 0; c < 10; ++c) {
        const int cp = c & 1;
        for (int it = 0; it < 10; ++it) {
            batch_bar();
            // ---- B: v = b / sum_of_partials ------------------------------
            {
                const float2* pb = (const float2*)(g_part[parity] + ((myb * MAXBLK) << 10));
                float2 kt = make_float2(0.f, 0.f);
                if (nbb == 19) {
#pragma unroll
                    for (int p = 0; p < 19; ++p) {
                        float2 x = __ldcg(pb + (p << 9) + tid);
                        kt.x += x.x; kt.y += x.y;
                    }
                } else {
                    for (int p = 0; p < nbb; ++p) {
                        float2 x = __ldcg(pb + (p << 9) + tid);
                        kt.x += x.x; kt.y += x.y;
                    }
                }
                float2 bb = ((const float2*)s_b)[tid];
                float vx = bb.x / kt.x;
                float vy = bb.y / kt.y;
                if (kt.x == 0.f || kt.y == 0.f ||
                    !(fabsf(vx) <= FLT_MAX) || !(fabsf(vy) <= FLT_MAX))
                    s_bad = 1;
                ((float2*)s_v[cp])[tid] = make_float2(vx, vy);
            }
            __syncthreads();
            // ---- u-pass: u_i = a_i / dot(K_row_i, v) ---------------------
            {
                const float4* v4 = (const float4*)s_v[cp];
                for (int r = wid; r < nr; r += NWB) {
                    const uint2* m2 = (const uint2*)(Kbh + ((size_t)(r_lo + r) << 10));
                    float d0 = 0.f, d1 = 0.f;
#pragma unroll
                    for (int cch = 0; cch < 8; cch += 2) {
                        uint2 q0 = __ldg(m2 + lane + 32 * cch);
                        uint2 q1 = __ldg(m2 + lane + 32 * (cch + 1));
                        float4 vv0 = v4[lane + 32 * cch];
                        float4 vv1 = v4[lane + 32 * (cch + 1)];
                        float2 a0 = h2f(q0.x), a1 = h2f(q0.y);
                        float2 b0 = h2f(q1.x), b1 = h2f(q1.y);
                        d0 = fmaf(a0.x, vv0.x, fmaf(a0.y, vv0.y,
                             fmaf(a1.x, vv0.z, fmaf(a1.y, vv0.w, d0))));
                        d1 = fmaf(b0.x, vv1.x, fmaf(b0.y, vv1.y,
                             fmaf(b1.x, vv1.z, fmaf(b1.y, vv1.w, d1))));
                    }
                    float dot = d0 + d1;
#pragma unroll
                    for (int o = 16; o; o >>= 1) dot += __shfl_xor_sync(0xffffffffu, dot, o);
                    if (lane == 0) {
                        float uu = s_a[r] / dot;
                        if (dot == 0.f || !(fabsf(uu) <= FLT_MAX)) s_bad = 1;
                        s_u[cp][r] = uu;
                    }
                }
            }
            __syncthreads();
            do_A(cp, parity ^ 1);
            parity ^= 1;
        }

        // ---- chunk check: maxdiff without materializing P -----------------
        {
            const float4* v4c = (const float4*)s_v[cp];
            const float4* v4p = (const float4*)s_v[cp ^ 1];
            float lm = 0.f;
            for (int r = wid; r < nr; r += NWB) {
                float u  = s_u[cp][r];
                float up = s_u[cp ^ 1][r];
                const uint2* k2 = (const uint2*)(Kbh + ((size_t)(r_lo + r) << 10));
#pragma unroll
                for (int cch = 0; cch < 8; ++cch) {
                    uint2 q = __ldg(k2 + lane + 32 * cch);
                    float2 f0 = h2f(q.x), f1 = h2f(q.y);
                    float4 vv = v4c[lane + 32 * cch];
                    float4 vp = v4p[lane + 32 * cch];
                    float dx = fabsf((u * f0.x) * vv.x - (up * f0.x) * vp.x);
                    float dy = fabsf((u * f0.y) * vv.y - (up * f0.y) * vp.y);
                    float dz = fabsf((u * f1.x) * vv.z - (up * f1.x) * vp.z);
                    float dw = fabsf((u * f1.y) * vv.w - (up * f1.y) * vp.w);
                    lm = fmaxf(lm, fmaxf(fmaxf(dx, dy), fmaxf(dz, dw)));
                }
            }
#pragma unroll
            for (int o = 16; o; o >>= 1) lm = fmaxf(lm, __shfl_xor_sync(0xffffffffu, lm, o));
            if (lane == 0) s_red[wid] = lm;
            __syncthreads();
            if (wid == 0) {
                float t = (lane < NWB) ? s_red[lane] : 0.f;
#pragma unroll
                for (int o = 16; o; o >>= 1) t = fmaxf(t, __shfl_xor_sync(0xffffffffu, t, o));
                if (lane == 0 && tid == 0) atomicMax(&g_maxdiff[c], __float_as_int(t));
            }
        }
        global_bar();                      // tid0's release orders its atomics
        if (tid == 0) {
            s_f0 = ld_cg_i(&g_bad);
            s_f1 = ld_cg_i(&g_maxdiff[c]);
        }
        __syncthreads();
        if (s_f0) {                        // bad: previous chunk's P (or P0)
            write_final(cp ^ 1);
            return;
        }
        if (__int_as_float(s_f1) < 1e-3f || c == 9) {
            write_final(cp);
            return;
        }
    }
}

extern "C" void kernel_launch(void* const* d_in, const int* in_sizes, int n_in,
                              void* d_out, int out_size) {
    static int nsm = 0;
    if (nsm == 0) {
        int dev = 0; cudaGetDevice(&dev);
        int v = 0;
        if (cudaDeviceGetAttribute(&v, cudaDevAttrMultiProcessorCount, dev)
                != cudaSuccess || v <= 0) v = 148;
        if (v > MAXG) v = MAXG;
        if (v < BATCH) v = BATCH;
        nsm = v;
    }
    const float* c1 = nullptr; const float* p1 = nullptr;
    const float* c2 = nullptr; const float* p2 = nullptr;
    for (int i = 0; i < n_in; ++i) {
        if (in_sizes[i] == BATCH * NPT * 2) {
            if (!c1) c1 = (const float*)d_in[i]; else c2 = (const float*)d_in[i];
        } else if (in_sizes[i] == BATCH * NPT) {
            if (!p1) p1 = (const float*)d_in[i]; else p2 = (const float*)d_in[i];
        }
    }
    sot_kernel<<<nsm, BLOCK>>>(c1, p1, c2, p2, (float*)d_out);
}